// round 12
// baseline (speedup 1.0000x reference)
#include <cuda_runtime.h>
#include <cuda_bf16.h>

#define S 128
#define TSTR 136   // tile row stride (floats); k>=64 skewed +4 floats (mid-row pad)
#define PS 132     // p buffer stride: slot(j) = j + (j>=64 ? 4 : 0)
#define NCTA 296   // persistent: 2 CTAs per SM
#define NTILE 2048

__device__ __align__(16) unsigned g_mrow[16 * S * 4];  // bit j: mask[b,i,j]
__device__ __align__(16) unsigned g_span[16 * S * 4];  // bit k: mask[b,j,k] | mask[b,k,j]

__device__ __forceinline__ float sigmoidf_(float x) {
    return 1.0f / (1.0f + __expf(-x));
}
__device__ __forceinline__ unsigned smem_u32(const void* p) {
    unsigned r;
    asm("{ .reg .u64 t; cvta.to.shared.u64 t, %1; cvt.u32.u64 %0, t; }" : "=r"(r) : "l"(p));
    return r;
}
#define CP_ASYNC16(dst, src) \
    asm volatile("cp.async.cg.shared.global [%0], [%1], 16;\n" :: "r"(dst), "l"(src))
#define CP_COMMIT() asm volatile("cp.async.commit_group;\n")
#define CP_WAIT0()  asm volatile("cp.async.wait_group 0;\n")

#define FMA2(acc, a, b) \
    asm("fma.rn.f32x2 %0, %1, %2, %3;" : "=l"(acc) : "l"(a), "l"(b), "l"(acc))
#define PACK2(d, x, y) \
    asm("mov.b64 %0, {%1, %2};" : "=l"(d) : "f"(x), "f"(y))
#define UNPACK2(x, y, d) \
    asm("mov.b64 {%0, %1}, %2;" : "=f"(x), "=f"(y) : "l"(d))

__device__ __forceinline__ unsigned pick_word(uint4 v, int wd) {
    return (wd == 0) ? v.x : (wd == 1) ? v.y : (wd == 2) ? v.z : v.w;
}

// ---- Pre-kernel: pack masks to bits; grid (16 batches x 4 j-quarters) ----
__global__ __launch_bounds__(512)
void mask_pack_kernel(const int* __restrict__ mask) {
    __shared__ unsigned char m[S * 132];
    const int b  = blockIdx.x;
    const int qy = blockIdx.y;
    const int t  = threadIdx.x;
    const int4* mg = reinterpret_cast<const int4*>(mask + (size_t)b * S * S);
    #pragma unroll
    for (int n = 0; n < 8; n++) {
        int idx = n * 512 + t;
        int row = idx >> 5, c4 = idx & 31;
        int4 v = __ldg(mg + idx);
        uchar4 u;
        u.x = (unsigned char)(v.x != 0); u.y = (unsigned char)(v.y != 0);
        u.z = (unsigned char)(v.z != 0); u.w = (unsigned char)(v.w != 0);
        *reinterpret_cast<uchar4*>(&m[row * 132 + (c4 << 2)]) = u;
    }
    __syncthreads();
    const int w = t >> 5, lane = t & 31;
    for (int task = w; task < 128; task += 16) {
        const int j  = (qy << 5) + (task >> 2);
        const int wd = task & 3;
        const int k  = (wd << 5) + lane;
        unsigned mjk = m[j * 132 + k];
        unsigned mkj = m[k * 132 + j];
        unsigned rw = __ballot_sync(0xffffffffu, mjk != 0);
        unsigned sw = __ballot_sync(0xffffffffu, (mjk | mkj) != 0);
        if (lane == 0) {
            g_mrow[(b * S + j) * 4 + wd] = rw;
            g_span[(b * S + j) * 4 + wd] = sw;
        }
    }
}

// ---- Main: persistent CTAs, warp-local smem-reuse pipeline, f32x2 FMA ----
extern __shared__ float sm[];

__global__ __launch_bounds__(256, 2)
void mfvi_main(const float* __restrict__ s_span,
               const float* __restrict__ s_pair,
               float* __restrict__ out)
{
    float* tile = sm;                    // S * TSTR (~69.6 KB), single buffer
    float* pA   = sm + S * TSTR;         // PS
    float* pB   = pA + PS;               // PS

    const int t    = threadIdx.x;
    const int lane = t & 31;
    const int w    = t >> 5;             // warp 0..7
    const int jj   = lane >> 1;
    const int h2   = lane & 1;           // k-half
    const int j    = (w << 4) + jj;
    const int cb   = h2 * 68;            // skewed column base

    const unsigned tb  = smem_u32(tile);
    const int co   = lane << 2;                      // src float col
    const int dco  = co + ((lane >= 16) ? 4 : 0);    // skewed dst col

    // ---- prologue: issue first tile's loads (warp-local rows) ----
    int n = blockIdx.x;
    uint4 mr = *reinterpret_cast<const uint4*>(&g_mrow[((n >> 7) * S + (n & 127)) * 4]);
    #pragma unroll
    for (int ii = 0; ii < 16; ii++) {
        const int r = (w << 4) + ii;
        if ((pick_word(mr, r >> 5) >> (r & 31)) & 1u)
            CP_ASYNC16(tb + (unsigned)((r * TSTR + dco) << 2),
                       s_pair + ((size_t)n * S + (size_t)r) * S + co);
    }
    CP_COMMIT();

    float* pa = pA;   // per-tile rotating p buffers
    float* pb = pB;

    for (; n < NTILE; n += NCTA) {
        const int b = n >> 7;
        const int i = n & 127;

        // ---- scalars + em words + p0 init (overlaps current tile's DRAM) ----
        float ssj = 0.f;
        if (h2 == 0) ssj = __ldg(&s_span[(size_t)n * S + j]);
        unsigned em0 = __ldg(&g_span[(b * S + j) * 4 + (h2 << 1) + 0]);
        unsigned em1 = __ldg(&g_span[(b * S + j) * 4 + (h2 << 1) + 1]);
        if (!((pick_word(mr, j >> 5) >> (j & 31)) & 1u)) { em0 = 0u; em1 = 0u; }
        {
            const int lo = min(i, j), hi = max(i, j);
            if ((lo >> 5) == (h2 << 1))     em0 &= ~(1u << (lo & 31));
            if ((lo >> 5) == (h2 << 1) + 1) em1 &= ~(1u << (lo & 31));
            if ((hi >> 5) == (h2 << 1))     em0 &= ~(1u << (hi & 31));
            if ((hi >> 5) == (h2 << 1) + 1) em1 &= ~(1u << (hi & 31));
        }
        if (t < S) {
            float v = __ldg(&s_span[(size_t)n * S + t]);
            pa[t + ((t >= 64) ? 4 : 0)] = sigmoidf_(v);
        }
        // prefetch next tile's row-mask
        const int nn = n + NCTA;
        uint4 mr_next = make_uint4(0u, 0u, 0u, 0u);
        if (nn < NTILE)
            mr_next = *reinterpret_cast<const uint4*>(
                &g_mrow[((nn >> 7) * S + (nn & 127)) * 4]);

        __syncthreads();   // bar1: p0 visible (iter-1 readers of pa protected by bar3)

        CP_WAIT0();        // current tile's rows landed

        // ---- readback + mask + pack into f32x2 registers (warp-local rows) ----
        unsigned long long M2[32];
        #pragma unroll
        for (int q = 0; q < 16; q++) {
            float4 v = *reinterpret_cast<const float4*>(&tile[j * TSTR + cb + (q << 2)]);
            const unsigned em = (q < 8) ? em0 : em1;
            const int sh = (q << 2) & 31;
            v.x = ((em >> (sh + 0)) & 1u) ? v.x : 0.f;
            v.y = ((em >> (sh + 1)) & 1u) ? v.y : 0.f;
            v.z = ((em >> (sh + 2)) & 1u) ? v.z : 0.f;
            v.w = ((em >> (sh + 3)) & 1u) ? v.w : 0.f;
            PACK2(M2[2*q],   v.x, v.y);
            PACK2(M2[2*q+1], v.z, v.w);
        }

        // ---- issue NEXT tile's loads into the same rows (warp-local, no barrier) ----
        if (nn < NTILE) {
            #pragma unroll
            for (int ii = 0; ii < 16; ii++) {
                const int r = (w << 4) + ii;
                if ((pick_word(mr_next, r >> 5) >> (r & 31)) & 1u)
                    CP_ASYNC16(tb + (unsigned)((r * TSTR + dco) << 2),
                               s_pair + ((size_t)nn * S + (size_t)r) * S + co);
            }
            CP_COMMIT();
        }
        mr = mr_next;

        // ---- 3 MFVI iterations: packed f32x2 FMA ----
        #pragma unroll
        for (int it = 0; it < 3; it++) {
            const float* pr = (it & 1) ? pb : pa;
            float*       pw = (it & 1) ? pa : pb;
            unsigned long long a0 = 0ull, a1 = 0ull, a2 = 0ull, a3 = 0ull;
            #pragma unroll
            for (int q = 0; q < 16; q += 2) {
                ulonglong2 pv0 = *reinterpret_cast<const ulonglong2*>(&pr[cb + (q << 2)]);
                ulonglong2 pv1 = *reinterpret_cast<const ulonglong2*>(&pr[cb + ((q + 1) << 2)]);
                FMA2(a0, pv0.x, M2[2*q]);
                FMA2(a1, pv0.y, M2[2*q+1]);
                FMA2(a2, pv1.x, M2[2*q+2]);
                FMA2(a3, pv1.y, M2[2*q+3]);
            }
            float x0, x1, y0, y1, z0, z1, w0, w1;
            UNPACK2(x0, x1, a0);
            UNPACK2(y0, y1, a1);
            UNPACK2(z0, z1, a2);
            UNPACK2(w0, w1, a3);
            float acc = ((x0 + x1) + (y0 + y1)) + ((z0 + z1) + (w0 + w1));
            acc += __shfl_xor_sync(0xffffffffu, acc, 1);
            if (it < 2) {
                if (h2 == 0)
                    pw[j + ((j >= 64) ? 4 : 0)] = sigmoidf_(ssj + acc);
                __syncthreads();                       // bars 2,3
            } else {
                if (h2 == 0)
                    out[(size_t)n * S + j] = sigmoidf_(ssj + acc);
                // no barrier: next tile's p-init writes pb (rotated), not pa
            }
        }

        // rotate p buffers for next tile
        float* tmp = pa; pa = pb; pb = tmp;
    }
}

extern "C" void kernel_launch(void* const* d_in, const int* in_sizes, int n_in,
                              void* d_out, int out_size) {
    const float* s_span = (const float*)d_in[0];
    const float* s_pair = (const float*)d_in[1];
    const int*   mask   = (const int*)d_in[2];
    float* out = (float*)d_out;

    const int smem_bytes = (S * TSTR + 2 * PS) * sizeof(float);  // ~70.7 KB
    cudaFuncSetAttribute(mfvi_main, cudaFuncAttributeMaxDynamicSharedMemorySize, smem_bytes);

    dim3 pg(16, 4);
    mask_pack_kernel<<<pg, 512>>>(mask);
    mfvi_main<<<NCTA, 256, smem_bytes>>>(s_span, s_pair, out);
}

// round 13
// speedup vs baseline: 1.1227x; 1.1227x over previous
#include <cuda_runtime.h>
#include <cuda_bf16.h>

#define S 128
#define TSTR 136   // tile row stride (floats); k>=64 skewed +4 (mid-row pad)
#define PS 132     // p buffer stride: slot(k) = k + (k>=64 ? 4 : 0)
#define NCTA 296   // persistent: 2 CTAs per SM
#define NTILE 2048

__device__ __align__(16) unsigned g_mrow[16 * S * 4];  // bit j: mask[b,i,j]
__device__ __align__(16) unsigned g_span[16 * S * 4];  // bit k: mask[b,j,k] | mask[b,k,j]

__device__ __forceinline__ float sigmoidf_(float x) {
    return 1.0f / (1.0f + __expf(-x));
}
__device__ __forceinline__ unsigned smem_u32(const void* p) {
    unsigned r;
    asm("{ .reg .u64 t; cvta.to.shared.u64 t, %1; cvt.u32.u64 %0, t; }" : "=r"(r) : "l"(p));
    return r;
}
#define CP_ASYNC16(dst, src) \
    asm volatile("cp.async.cg.shared.global [%0], [%1], 16;\n" :: "r"(dst), "l"(src))
#define CP_COMMIT() asm volatile("cp.async.commit_group;\n")
#define CP_WAIT0()  asm volatile("cp.async.wait_group 0;\n")

#define FMA2(acc, a, b) \
    asm("fma.rn.f32x2 %0, %1, %2, %3;" : "=l"(acc) : "l"(a), "l"(b), "l"(acc))
#define PACK2(d, x, y) \
    asm("mov.b64 %0, {%1, %2};" : "=l"(d) : "f"(x), "f"(y))
#define UNPACK2(x, y, d) \
    asm("mov.b64 {%0, %1}, %2;" : "=f"(x), "=f"(y) : "l"(d))

__device__ __forceinline__ unsigned pick_word(uint4 v, int wd) {
    return (wd == 0) ? v.x : (wd == 1) ? v.y : (wd == 2) ? v.z : v.w;
}
__device__ __forceinline__ int popc4(uint4 v) {
    return __popc(v.x) + __popc(v.y) + __popc(v.z) + __popc(v.w);
}
// number of set bits strictly below bit t
__device__ __forceinline__ int prefix_pos(uint4 v, int t) {
    const int wd = t >> 5, sh = t & 31;
    int c = __popc(pick_word(v, wd) & ((1u << sh) - 1u));
    if (wd > 0) c += __popc(v.x);
    if (wd > 1) c += __popc(v.y);
    if (wd > 2) c += __popc(v.z);
    return c;
}
__device__ __forceinline__ int slotf(int k) { return k + ((k >= 64) ? 4 : 0); }

// ---- Pre-kernel: pack masks to bits; grid (16 batches x 4 j-quarters) ----
__global__ __launch_bounds__(512)
void mask_pack_kernel(const int* __restrict__ mask) {
    __shared__ unsigned char m[S * 132];
    const int b  = blockIdx.x;
    const int qy = blockIdx.y;
    const int t  = threadIdx.x;
    const int4* mg = reinterpret_cast<const int4*>(mask + (size_t)b * S * S);
    #pragma unroll
    for (int n = 0; n < 8; n++) {
        int idx = n * 512 + t;
        int row = idx >> 5, c4 = idx & 31;
        int4 v = __ldg(mg + idx);
        uchar4 u;
        u.x = (unsigned char)(v.x != 0); u.y = (unsigned char)(v.y != 0);
        u.z = (unsigned char)(v.z != 0); u.w = (unsigned char)(v.w != 0);
        *reinterpret_cast<uchar4*>(&m[row * 132 + (c4 << 2)]) = u;
    }
    __syncthreads();
    const int w = t >> 5, lane = t & 31;
    for (int task = w; task < 128; task += 16) {
        const int j  = (qy << 5) + (task >> 2);
        const int wd = task & 3;
        const int k  = (wd << 5) + lane;
        unsigned mjk = m[j * 132 + k];
        unsigned mkj = m[k * 132 + j];
        unsigned rw = __ballot_sync(0xffffffffu, mjk != 0);
        unsigned sw = __ballot_sync(0xffffffffu, (mjk | mkj) != 0);
        if (lane == 0) {
            g_mrow[(b * S + j) * 4 + wd] = rw;
            g_span[(b * S + j) * 4 + wd] = sw;
        }
    }
}

// ---- Main: persistent CTAs, live-row compaction, warp-prefix active sets ----
extern __shared__ float sm[];

__global__ __launch_bounds__(256, 2)
void mfvi_main(const float* __restrict__ s_span,
               const float* __restrict__ s_pair,
               float* __restrict__ out)
{
    float* tile = sm;                    // S * TSTR floats (compacted live rows)
    float* pA   = sm + S * TSTR;
    float* pB   = pA + PS;
    int*   lsA  = (int*)(pB + PS);       // live-row lists (slot -> row)
    int*   lsB  = lsA + S;

    const int t    = threadIdx.x;
    const int lane = t & 31;
    const int w    = t >> 5;             // warp 0..7
    const int lr   = t >> 1;             // compacted slot this thread consumes
    const int h2   = t & 1;              // k-half
    const int cb   = h2 * 68;            // skewed column base

    const unsigned tb  = smem_u32(tile);
    const int co  = lane << 2;
    const int dco = co + ((lane >= 16) ? 4 : 0);

    // ---- prologue: first tile's live list + loads ----
    int n = blockIdx.x;
    uint4 mr = *reinterpret_cast<const uint4*>(&g_mrow[((n >> 7) * S + (n & 127)) * 4]);
    int Lcur = popc4(mr);
    if (t < S) {
        if ((pick_word(mr, t >> 5) >> (t & 31)) & 1u)
            lsA[prefix_pos(mr, t)] = t;
    }
    __syncthreads();
    for (int s = w; s < Lcur; s += 8) {
        const int r = lsA[s];
        CP_ASYNC16(tb + (unsigned)((s * TSTR + dco) << 2),
                   s_pair + ((size_t)n * S + (size_t)r) * S + co);
    }
    CP_COMMIT();

    int*   lscur = lsA; int* lsnext = lsB;
    float* pa = pA;     float* pb = pB;

    for (; n < NTILE; n += NCTA) {
        const int b = n >> 7;
        const int i = n & 127;
        const int nn = n + NCTA;
        uint4 mr_next = make_uint4(0u, 0u, 0u, 0u);
        if (nn < NTILE)
            mr_next = *reinterpret_cast<const uint4*>(
                &g_mrow[((nn >> 7) * S + (nn & 127)) * 4]);
        const int Lnext = popc4(mr_next);

        // ---- scalar phase (overlaps current tile's DRAM) ----
        bool  deadr = false;
        float pvv   = 0.f;
        if (t < S) {
            float v = __ldg(&s_span[(size_t)n * S + t]);
            pvv = sigmoidf_(v);
            pa[slotf(t)] = pvv;                       // p0 for ALL rows
            if (!((pick_word(mr, t >> 5) >> (t & 31)) & 1u)) {
                deadr = true;
                out[(size_t)n * S + t] = pvv;         // dead row: final output now
            }
            if (nn < NTILE) {
                if ((pick_word(mr_next, t >> 5) >> (t & 31)) & 1u)
                    lsnext[prefix_pos(mr_next, t)] = t;
            }
        }
        // active mapping + em words (lscur visible via prior barriers)
        const bool act = lr < Lcur;
        int j = 0; float ssj = 0.f; unsigned em0 = 0u, em1 = 0u;
        if (act) {
            j = lscur[lr];
            if (h2 == 0) ssj = __ldg(&s_span[(size_t)n * S + j]);
            em0 = __ldg(&g_span[(b * S + j) * 4 + (h2 << 1) + 0]);
            em1 = __ldg(&g_span[(b * S + j) * 4 + (h2 << 1) + 1]);
            const int lo = min(i, j), hi = max(i, j);
            if ((lo >> 5) == (h2 << 1))     em0 &= ~(1u << (lo & 31));
            if ((lo >> 5) == (h2 << 1) + 1) em1 &= ~(1u << (lo & 31));
            if ((hi >> 5) == (h2 << 1))     em0 &= ~(1u << (hi & 31));
            if ((hi >> 5) == (h2 << 1) + 1) em1 &= ~(1u << (hi & 31));
        }

        CP_WAIT0();
        __syncthreads();   // bar_A: tile data + p0 + live lists visible

        // dead rows: constant p into the iter-1 read buffer too
        if (deadr) pb[slotf(t)] = pvv;

        // ---- readback + mask + pack (active threads only, compacted slots) ----
        unsigned long long M2[32];
        if (act) {
            #pragma unroll
            for (int q = 0; q < 16; q++) {
                float4 v = *reinterpret_cast<const float4*>(&tile[lr * TSTR + cb + (q << 2)]);
                const unsigned em = (q < 8) ? em0 : em1;
                const int sh = (q << 2) & 31;
                v.x = ((em >> (sh + 0)) & 1u) ? v.x : 0.f;
                v.y = ((em >> (sh + 1)) & 1u) ? v.y : 0.f;
                v.z = ((em >> (sh + 2)) & 1u) ? v.z : 0.f;
                v.w = ((em >> (sh + 3)) & 1u) ? v.w : 0.f;
                PACK2(M2[2*q],   v.x, v.y);
                PACK2(M2[2*q+1], v.z, v.w);
            }
        }

        __syncthreads();   // bar_B: readback done before slot reuse

        // ---- issue next tile's loads into compacted slots ----
        if (nn < NTILE) {
            for (int s = w; s < Lnext; s += 8) {
                const int r = lsnext[s];
                CP_ASYNC16(tb + (unsigned)((s * TSTR + dco) << 2),
                           s_pair + ((size_t)nn * S + (size_t)r) * S + co);
            }
        }
        CP_COMMIT();

        // ---- 3 MFVI iterations (active threads; warp-prefix shfl masks) ----
        const int pairsw = min(max(Lcur - (w << 4), 0), 16);
        const unsigned smask = (pairsw >= 16) ? 0xffffffffu
                             : ((pairsw <= 0) ? 0u : ((1u << (pairsw << 1)) - 1u));
        #pragma unroll
        for (int it = 0; it < 3; it++) {
            const float* pr = (it & 1) ? pb : pa;
            float*       pw = (it & 1) ? pa : pb;
            if (act) {
                unsigned long long a0 = 0ull, a1 = 0ull, a2 = 0ull, a3 = 0ull;
                #pragma unroll
                for (int q = 0; q < 16; q += 2) {
                    ulonglong2 pv0 = *reinterpret_cast<const ulonglong2*>(&pr[cb + (q << 2)]);
                    ulonglong2 pv1 = *reinterpret_cast<const ulonglong2*>(&pr[cb + ((q + 1) << 2)]);
                    FMA2(a0, pv0.x, M2[2*q]);
                    FMA2(a1, pv0.y, M2[2*q+1]);
                    FMA2(a2, pv1.x, M2[2*q+2]);
                    FMA2(a3, pv1.y, M2[2*q+3]);
                }
                float x0, x1, y0, y1, z0, z1, w0, w1;
                UNPACK2(x0, x1, a0);
                UNPACK2(y0, y1, a1);
                UNPACK2(z0, z1, a2);
                UNPACK2(w0, w1, a3);
                float acc = ((x0 + x1) + (y0 + y1)) + ((z0 + z1) + (w0 + w1));
                acc += __shfl_xor_sync(smask, acc, 1);
                if (h2 == 0) {
                    if (it < 2) pw[slotf(j)] = sigmoidf_(ssj + acc);
                    else        out[(size_t)n * S + j] = sigmoidf_(ssj + acc);
                }
            }
            if (it < 2) __syncthreads();   // bars 2,3
            // it==2: no barrier — next tile's p-init writes the rotated buffer
        }

        // rotate per-tile state
        { float* tp = pa; pa = pb; pb = tp; }
        { int*   tp = lscur; lscur = lsnext; lsnext = tp; }
        mr = mr_next;
        Lcur = Lnext;
    }
}

extern "C" void kernel_launch(void* const* d_in, const int* in_sizes, int n_in,
                              void* d_out, int out_size) {
    const float* s_span = (const float*)d_in[0];
    const float* s_pair = (const float*)d_in[1];
    const int*   mask   = (const int*)d_in[2];
    float* out = (float*)d_out;

    const int smem_bytes = (S * TSTR + 2 * PS) * sizeof(float) + 2 * S * sizeof(int);
    cudaFuncSetAttribute(mfvi_main, cudaFuncAttributeMaxDynamicSharedMemorySize, smem_bytes);

    dim3 pg(16, 4);
    mask_pack_kernel<<<pg, 512>>>(mask);
    mfvi_main<<<NCTA, 256, smem_bytes>>>(s_span, s_pair, out);
}